// round 3
// baseline (speedup 1.0000x reference)
#include <cuda_runtime.h>
#include <cuda_bf16.h>

// ---------------------------------------------------------------------------
// Problem constants
// ---------------------------------------------------------------------------
#define BATCH   4
#define SEQ     2048
#define DIM     768
#define NHEADS  12
#define HDIM    64
#define MROWS   (BATCH * SEQ)          // 8192

// Scratch: Q, K, V in [B, H, N, D] layout (fp32). 3 x 25.2 MB static device mem.
__device__ float g_Q[BATCH * NHEADS * SEQ * HDIM];
__device__ float g_K[BATCH * NHEADS * SEQ * HDIM];
__device__ float g_V[BATCH * NHEADS * SEQ * HDIM];

// ---------------------------------------------------------------------------
// QKV projection GEMM:  out[m, c] = sum_k x[m,k] * w[c,k] + bias[c]
// Both x and w are K-contiguous (NT gemm). Tile 128x128x8, 256 threads,
// 8x8 per-thread microtile. Epilogue scatters into [B,H,N,D] scratch.
// ---------------------------------------------------------------------------
#define BM 128
#define BN 128
#define BK 8

__global__ __launch_bounds__(256)
void qkv_gemm_kernel(const float* __restrict__ x,
                     const float* __restrict__ w,
                     const float* __restrict__ bias,
                     float* __restrict__ dst /* [B,H,N,D] */) {
    __shared__ float As[BK][BM];
    __shared__ float Bs[BK][BN];

    const int tid = threadIdx.x;           // 0..255
    const int m0  = blockIdx.x * BM;       // row tile
    const int c0  = blockIdx.y * BN;       // col tile

    // load mapping: each thread loads one float4 of A and one of B per K-tile
    const int lrow = tid >> 1;             // 0..127
    const int lk   = (tid & 1) * 4;        // 0 or 4
    const float* aptr = x + (size_t)(m0 + lrow) * DIM + lk;
    const float* bptr = w + (size_t)(c0 + lrow) * DIM + lk;

    // compute mapping: 16x16 thread grid of 8x8 microtiles
    const int tm = (tid >> 4) * 8;
    const int tn = (tid & 15) * 8;

    float acc[8][8];
#pragma unroll
    for (int i = 0; i < 8; i++)
#pragma unroll
        for (int j = 0; j < 8; j++) acc[i][j] = 0.f;

    for (int k0 = 0; k0 < DIM; k0 += BK) {
        float4 av = *reinterpret_cast<const float4*>(aptr + k0);
        float4 bv = *reinterpret_cast<const float4*>(bptr + k0);
        As[lk + 0][lrow] = av.x;
        As[lk + 1][lrow] = av.y;
        As[lk + 2][lrow] = av.z;
        As[lk + 3][lrow] = av.w;
        Bs[lk + 0][lrow] = bv.x;
        Bs[lk + 1][lrow] = bv.y;
        Bs[lk + 2][lrow] = bv.z;
        Bs[lk + 3][lrow] = bv.w;
        __syncthreads();

#pragma unroll
        for (int k = 0; k < BK; k++) {
            float4 a0 = *reinterpret_cast<const float4*>(&As[k][tm]);
            float4 a1 = *reinterpret_cast<const float4*>(&As[k][tm + 4]);
            float4 b0 = *reinterpret_cast<const float4*>(&Bs[k][tn]);
            float4 b1 = *reinterpret_cast<const float4*>(&Bs[k][tn + 4]);
            float ar[8] = {a0.x, a0.y, a0.z, a0.w, a1.x, a1.y, a1.z, a1.w};
            float br[8] = {b0.x, b0.y, b0.z, b0.w, b1.x, b1.y, b1.z, b1.w};
#pragma unroll
            for (int i = 0; i < 8; i++)
#pragma unroll
                for (int j = 0; j < 8; j++)
                    acc[i][j] = fmaf(ar[i], br[j], acc[i][j]);
        }
        __syncthreads();
    }

    // Epilogue: add bias, scatter to [B,H,N,D]
#pragma unroll
    for (int i = 0; i < 8; i++) {
        const int m = m0 + tm + i;
        const int b = m >> 11;          // m / 2048
        const int n = m & 2047;
#pragma unroll
        for (int j = 0; j < 8; j++) {
            const int c = c0 + tn + j;
            const int h = c >> 6;       // c / 64
            const int d = c & 63;
            const size_t idx = (((size_t)(b * NHEADS + h)) * SEQ + n) * HDIM + d;
            dst[idx] = acc[i][j] + bias[c];
        }
    }
}

// ---------------------------------------------------------------------------
// Flash attention (fp32). One block = (b, h, 128 query rows); 128 threads,
// one query row per thread. K/V staged in 64x64 smem tiles; online softmax
// with rescale-only-when-max-improves.
// ---------------------------------------------------------------------------
#define QTILE 128
#define KTILE 64

__device__ __forceinline__ float dot4(float4 a, float4 b) {
    return fmaf(a.x, b.x, fmaf(a.y, b.y, fmaf(a.z, b.z, a.w * b.w)));
}

__global__ __launch_bounds__(QTILE)
void attn_kernel(const float* __restrict__ Q,
                 const float* __restrict__ K,
                 const float* __restrict__ V,
                 float* __restrict__ out /* [B,N,DIM] */) {
    __shared__ float Ks[KTILE][HDIM];
    __shared__ float Vs[KTILE][HDIM];

    const int tid = threadIdx.x;                       // 0..127
    const int nqt = SEQ / QTILE;                       // 16
    const int bh  = blockIdx.x / nqt;                  // 0..47
    const int qt  = blockIdx.x % nqt;
    const int b   = bh / NHEADS;
    const int h   = bh % NHEADS;
    const int row = qt * QTILE + tid;

    // Load q row into registers (16 float4)
    const float4* qptr =
        reinterpret_cast<const float4*>(Q + ((size_t)bh * SEQ + row) * HDIM);
    float4 q[16];
#pragma unroll
    for (int i = 0; i < 16; i++) q[i] = qptr[i];

    float4 acc[16];
#pragma unroll
    for (int i = 0; i < 16; i++) acc[i] = make_float4(0.f, 0.f, 0.f, 0.f);
    float mval = -1e30f;
    float lsum = 0.f;

    const float scale = 0.125f;   // 64^-0.5

    for (int kt = 0; kt < SEQ / KTILE; kt++) {
        // stage K/V tile: 64x64 floats each = 1024 float4s; 8 per thread
        const float4* kg = reinterpret_cast<const float4*>(
            K + ((size_t)bh * SEQ + kt * KTILE) * HDIM);
        const float4* vg = reinterpret_cast<const float4*>(
            V + ((size_t)bh * SEQ + kt * KTILE) * HDIM);
        float4* ks_s = reinterpret_cast<float4*>(&Ks[0][0]);
        float4* vs_s = reinterpret_cast<float4*>(&Vs[0][0]);
#pragma unroll
        for (int t = 0; t < 8; t++) {
            const int idx = t * QTILE + tid;           // 0..1023
            ks_s[idx] = kg[idx];
            vs_s[idx] = vg[idx];
        }
        __syncthreads();

        for (int j = 0; j < KTILE; j++) {
            const float4* krow = reinterpret_cast<const float4*>(&Ks[j][0]);
            float s0 = 0.f, s1 = 0.f, s2 = 0.f, s3 = 0.f;
#pragma unroll
            for (int i = 0; i < 16; i += 4) {
                s0 += dot4(q[i + 0], krow[i + 0]);
                s1 += dot4(q[i + 1], krow[i + 1]);
                s2 += dot4(q[i + 2], krow[i + 2]);
                s3 += dot4(q[i + 3], krow[i + 3]);
            }
            float s = ((s0 + s1) + (s2 + s3)) * scale;

            if (s > mval) {
                const float alpha = __expf(mval - s);  // exp(-1e30-…)=0 first time
                lsum *= alpha;
#pragma unroll
                for (int i = 0; i < 16; i++) {
                    acc[i].x *= alpha; acc[i].y *= alpha;
                    acc[i].z *= alpha; acc[i].w *= alpha;
                }
                mval = s;
            }
            const float p = __expf(s - mval);
            lsum += p;

            const float4* vrow = reinterpret_cast<const float4*>(&Vs[j][0]);
#pragma unroll
            for (int i = 0; i < 16; i++) {
                const float4 vv = vrow[i];
                acc[i].x = fmaf(p, vv.x, acc[i].x);
                acc[i].y = fmaf(p, vv.y, acc[i].y);
                acc[i].z = fmaf(p, vv.z, acc[i].z);
                acc[i].w = fmaf(p, vv.w, acc[i].w);
            }
        }
        __syncthreads();
    }

    const float inv = 1.0f / lsum;
    float4* optr = reinterpret_cast<float4*>(
        out + ((size_t)b * SEQ + row) * DIM + h * HDIM);
#pragma unroll
    for (int i = 0; i < 16; i++) {
        float4 v = acc[i];
        v.x *= inv; v.y *= inv; v.z *= inv; v.w *= inv;
        optr[i] = v;
    }
}

// ---------------------------------------------------------------------------
// launch
// ---------------------------------------------------------------------------
extern "C" void kernel_launch(void* const* d_in, const int* in_sizes, int n_in,
                              void* d_out, int out_size) {
    const float* x  = (const float*)d_in[0];
    const float* wq = (const float*)d_in[1];
    const float* bq = (const float*)d_in[2];
    const float* wk = (const float*)d_in[3];
    const float* bk = (const float*)d_in[4];
    const float* wv = (const float*)d_in[5];
    const float* bv = (const float*)d_in[6];
    float* out = (float*)d_out;

    float* qbuf; cudaGetSymbolAddress((void**)&qbuf, g_Q);
    float* kbuf; cudaGetSymbolAddress((void**)&kbuf, g_K);
    float* vbuf; cudaGetSymbolAddress((void**)&vbuf, g_V);

    dim3 gemm_grid(MROWS / BM, DIM / BN);   // 64 x 6
    qkv_gemm_kernel<<<gemm_grid, 256>>>(x, wq, bq, qbuf);
    qkv_gemm_kernel<<<gemm_grid, 256>>>(x, wk, bk, kbuf);
    qkv_gemm_kernel<<<gemm_grid, 256>>>(x, wv, bv, vbuf);

    dim3 attn_grid(BATCH * NHEADS * (SEQ / QTILE));  // 768
    attn_kernel<<<attn_grid, QTILE>>>(qbuf, kbuf, vbuf, out);
}

// round 4
// speedup vs baseline: 2.3119x; 2.3119x over previous
#include <cuda_runtime.h>
#include <cuda_fp16.h>
#include <cstdint>

// ---------------------------------------------------------------------------
// Problem constants
// ---------------------------------------------------------------------------
#define BATCH   4
#define SEQ     2048
#define DIM     768
#define NHEADS  12
#define HDIM    64
#define MROWS   (BATCH * SEQ)          // 8192

// Scratch: Q, K, V in [B, H, N, D] layout, fp16 (Q pre-scaled by 1/8).
__device__ __half g_Q[BATCH * NHEADS * SEQ * HDIM];
__device__ __half g_K[BATCH * NHEADS * SEQ * HDIM];
__device__ __half g_V[BATCH * NHEADS * SEQ * HDIM];

// ---------------------------------------------------------------------------
// QKV projection GEMM (fp32 compute, fp16 output):
//   out[m, c] = (sum_k x[m,k] * w[c,k] + bias[c]) * scale
// ---------------------------------------------------------------------------
#define BM 128
#define BN 128
#define BK 8

__global__ __launch_bounds__(256)
void qkv_gemm_kernel(const float* __restrict__ x,
                     const float* __restrict__ w,
                     const float* __restrict__ bias,
                     __half* __restrict__ dst /* [B,H,N,D] fp16 */,
                     float scale) {
    __shared__ float As[BK][BM];
    __shared__ float Bs[BK][BN];

    const int tid = threadIdx.x;
    const int m0  = blockIdx.x * BM;
    const int c0  = blockIdx.y * BN;

    const int lrow = tid >> 1;
    const int lk   = (tid & 1) * 4;
    const float* aptr = x + (size_t)(m0 + lrow) * DIM + lk;
    const float* bptr = w + (size_t)(c0 + lrow) * DIM + lk;

    const int tm = (tid >> 4) * 8;
    const int tn = (tid & 15) * 8;

    float acc[8][8];
#pragma unroll
    for (int i = 0; i < 8; i++)
#pragma unroll
        for (int j = 0; j < 8; j++) acc[i][j] = 0.f;

    for (int k0 = 0; k0 < DIM; k0 += BK) {
        float4 av = *reinterpret_cast<const float4*>(aptr + k0);
        float4 bv = *reinterpret_cast<const float4*>(bptr + k0);
        As[lk + 0][lrow] = av.x;  As[lk + 1][lrow] = av.y;
        As[lk + 2][lrow] = av.z;  As[lk + 3][lrow] = av.w;
        Bs[lk + 0][lrow] = bv.x;  Bs[lk + 1][lrow] = bv.y;
        Bs[lk + 2][lrow] = bv.z;  Bs[lk + 3][lrow] = bv.w;
        __syncthreads();

#pragma unroll
        for (int k = 0; k < BK; k++) {
            float4 a0 = *reinterpret_cast<const float4*>(&As[k][tm]);
            float4 a1 = *reinterpret_cast<const float4*>(&As[k][tm + 4]);
            float4 b0 = *reinterpret_cast<const float4*>(&Bs[k][tn]);
            float4 b1 = *reinterpret_cast<const float4*>(&Bs[k][tn + 4]);
            float ar[8] = {a0.x, a0.y, a0.z, a0.w, a1.x, a1.y, a1.z, a1.w};
            float br[8] = {b0.x, b0.y, b0.z, b0.w, b1.x, b1.y, b1.z, b1.w};
#pragma unroll
            for (int i = 0; i < 8; i++)
#pragma unroll
                for (int j = 0; j < 8; j++)
                    acc[i][j] = fmaf(ar[i], br[j], acc[i][j]);
        }
        __syncthreads();
    }

    // Epilogue: bias + scale, pack 8 halves -> one uint4 store, [B,H,N,D]
    const int h  = (c0 + tn) >> 6;
    const int d0 = (c0 + tn) & 63;
#pragma unroll
    for (int i = 0; i < 8; i++) {
        const int m = m0 + tm + i;
        const int b = m >> 11;
        const int n = m & 2047;
        __half hv[8];
#pragma unroll
        for (int j = 0; j < 8; j++)
            hv[j] = __float2half((acc[i][j] + bias[c0 + tn + j]) * scale);
        const size_t idx = (((size_t)(b * NHEADS + h)) * SEQ + n) * HDIM + d0;
        *reinterpret_cast<uint4*>(&dst[idx]) = *reinterpret_cast<uint4*>(hv);
    }
}

// ---------------------------------------------------------------------------
// Flash attention with fp16 mma.sync tensor cores.
//   block = (b, h, 128 q-rows); 8 warps x 16 rows; 64-key tiles.
// ---------------------------------------------------------------------------
#define LOG2E 1.4426950408889634f
#define SWZ(o) ((o) ^ (((o) >> 3) & 0x70))   // SW128 swizzle for 128B rows

__device__ __forceinline__ float fast_exp2(float x) {
    // 2^x for x <= 0 (clamped), FMA-pipe only. rel err ~2.4e-6.
    x = fmaxf(x, -120.f);
    float fn = rintf(x);
    float f  = x - fn;                 // f in [-0.5, 0.5]
    float p  = 1.3333558e-3f;
    p = fmaf(p, f, 9.6181291e-3f);
    p = fmaf(p, f, 5.5504109e-2f);
    p = fmaf(p, f, 2.4022651e-1f);
    p = fmaf(p, f, 6.9314718e-1f);
    p = fmaf(p, f, 1.0f);
    return __int_as_float(((int)fn + 127) << 23) * p;
}

__device__ __forceinline__ void ldsm_x4(uint32_t& r0, uint32_t& r1,
                                        uint32_t& r2, uint32_t& r3,
                                        uint32_t addr) {
    asm volatile("ldmatrix.sync.aligned.m8n8.x4.shared.b16 {%0,%1,%2,%3}, [%4];"
                 : "=r"(r0), "=r"(r1), "=r"(r2), "=r"(r3) : "r"(addr));
}

__device__ __forceinline__ void ldsm_x4_t(uint32_t& r0, uint32_t& r1,
                                          uint32_t& r2, uint32_t& r3,
                                          uint32_t addr) {
    asm volatile("ldmatrix.sync.aligned.m8n8.x4.trans.shared.b16 {%0,%1,%2,%3}, [%4];"
                 : "=r"(r0), "=r"(r1), "=r"(r2), "=r"(r3) : "r"(addr));
}

__device__ __forceinline__ void mma16816(float* c, const uint32_t* a,
                                         const uint32_t b0, const uint32_t b1) {
    asm volatile("mma.sync.aligned.m16n8k16.row.col.f32.f16.f16.f32 "
                 "{%0,%1,%2,%3}, {%4,%5,%6,%7}, {%8,%9}, {%0,%1,%2,%3};"
                 : "+f"(c[0]), "+f"(c[1]), "+f"(c[2]), "+f"(c[3])
                 : "r"(a[0]), "r"(a[1]), "r"(a[2]), "r"(a[3]), "r"(b0), "r"(b1));
}

__global__ __launch_bounds__(256)
void attn_kernel(const __half* __restrict__ Q,
                 const __half* __restrict__ K,
                 const __half* __restrict__ V,
                 float* __restrict__ out /* [B,N,DIM] fp32 */) {
    __shared__ __align__(16) char qs[128 * 128];  // 128 rows x 128B (64 halves)
    __shared__ __align__(16) char ks[64 * 128];
    __shared__ __align__(16) char vs[64 * 128];

    const int tid  = threadIdx.x;
    const int lane = tid & 31;
    const int warp = tid >> 5;

    const int nqt = SEQ / 128;                   // 16
    const int bh  = blockIdx.x / nqt;
    const int qt  = blockIdx.x % nqt;
    const int b   = bh / NHEADS;
    const int h   = bh % NHEADS;

    const uint32_t qs_base = (uint32_t)__cvta_generic_to_shared(qs);
    const uint32_t ks_base = (uint32_t)__cvta_generic_to_shared(ks);
    const uint32_t vs_base = (uint32_t)__cvta_generic_to_shared(vs);

    // ---- stage Q tile (128 x 64 fp16) into swizzled smem -------------------
    {
        const uint4* g = reinterpret_cast<const uint4*>(
            Q + ((size_t)bh * SEQ + qt * 128) * HDIM);
#pragma unroll
        for (int c = tid; c < 1024; c += 256) {
            int off = c * 16;
            *reinterpret_cast<uint4*>(qs + SWZ(off)) = g[c];
        }
    }
    __syncthreads();

    const int grp = lane >> 3;          // 0..3 (ldmatrix octet)
    const int l7  = lane & 7;

    // ---- Q A-fragments: 4 k-chunks (d=16 each), kept in registers ----------
    uint32_t qa[4][4];
    {
        // m0: rows 0-7 @klo, m1: rows 8-15 @klo, m2: rows 0-7 @khi, m3: rows 8-15 @khi
        const int qrow  = warp * 16 + ((grp & 1) << 3) + l7;
        const int qcolb = (grp >> 1) << 4;
#pragma unroll
        for (int kc = 0; kc < 4; kc++) {
            int off = qrow * 128 + kc * 32 + qcolb;
            ldsm_x4(qa[kc][0], qa[kc][1], qa[kc][2], qa[kc][3], qs_base + SWZ(off));
        }
    }

    // ldmatrix lane patterns for K (no trans) and V (trans)
    const int k_rl   = ((grp >> 1) << 3) + l7;   // key-row within n-pair
    const int k_colb = (grp & 1) << 4;           // d 16B-chunk select
    const int v_rl   = ((grp & 1) << 3) + l7;    // key-row within k-chunk
    const int v_colb = (grp >> 1) << 4;          // d-tile select within pair

    float Oacc[8][4];
#pragma unroll
    for (int j = 0; j < 8; j++)
#pragma unroll
        for (int r = 0; r < 4; r++) Oacc[j][r] = 0.f;
    float m_lo = -1e30f, m_hi = -1e30f, l_lo = 0.f, l_hi = 0.f;

    for (int kt = 0; kt < SEQ / 64; kt++) {
        // ---- stage K,V tiles (64 x 64 fp16 each) ---------------------------
        const uint4* kg = reinterpret_cast<const uint4*>(
            K + ((size_t)bh * SEQ + kt * 64) * HDIM);
        const uint4* vg = reinterpret_cast<const uint4*>(
            V + ((size_t)bh * SEQ + kt * 64) * HDIM);
#pragma unroll
        for (int c = tid; c < 512; c += 256) {
            int off = c * 16;
            *reinterpret_cast<uint4*>(ks + SWZ(off)) = kg[c];
            *reinterpret_cast<uint4*>(vs + SWZ(off)) = vg[c];
        }
        __syncthreads();

        // ---- S = Q K^T  (8 n-tiles of 8 keys) ------------------------------
        float S[8][4];
#pragma unroll
        for (int j = 0; j < 8; j++)
#pragma unroll
            for (int r = 0; r < 4; r++) S[j][r] = 0.f;

#pragma unroll
        for (int np = 0; np < 4; np++) {         // key 16-row pairs
#pragma unroll
            for (int kc = 0; kc < 4; kc++) {     // d 16-chunks
                uint32_t b0, b1, b2, b3;
                int off = (np * 16 + k_rl) * 128 + kc * 32 + k_colb;
                ldsm_x4(b0, b1, b2, b3, ks_base + SWZ(off));
                mma16816(S[2 * np],     qa[kc], b0, b1);
                mma16816(S[2 * np + 1], qa[kc], b2, b3);
            }
        }

        // ---- online softmax ------------------------------------------------
        float tmax_lo = -1e30f, tmax_hi = -1e30f;
#pragma unroll
        for (int j = 0; j < 8; j++) {
            tmax_lo = fmaxf(tmax_lo, fmaxf(S[j][0], S[j][1]));
            tmax_hi = fmaxf(tmax_hi, fmaxf(S[j][2], S[j][3]));
        }
        tmax_lo = fmaxf(tmax_lo, __shfl_xor_sync(0xffffffffu, tmax_lo, 1));
        tmax_lo = fmaxf(tmax_lo, __shfl_xor_sync(0xffffffffu, tmax_lo, 2));
        tmax_hi = fmaxf(tmax_hi, __shfl_xor_sync(0xffffffffu, tmax_hi, 1));
        tmax_hi = fmaxf(tmax_hi, __shfl_xor_sync(0xffffffffu, tmax_hi, 2));

        const float mnew_lo = fmaxf(m_lo, tmax_lo);
        const float mnew_hi = fmaxf(m_hi, tmax_hi);
        const float scl_lo = fast_exp2((m_lo - mnew_lo) * LOG2E);
        const float scl_hi = fast_exp2((m_hi - mnew_hi) * LOG2E);
        m_lo = mnew_lo;  m_hi = mnew_hi;
        l_lo *= scl_lo;  l_hi *= scl_hi;
#pragma unroll
        for (int j = 0; j < 8; j++) {
            Oacc[j][0] *= scl_lo; Oacc[j][1] *= scl_lo;
            Oacc[j][2] *= scl_hi; Oacc[j][3] *= scl_hi;
        }

        const float mb_lo = mnew_lo * LOG2E;
        const float mb_hi = mnew_hi * LOG2E;
        uint32_t P[8][2];
        float rs_lo = 0.f, rs_hi = 0.f;
#pragma unroll
        for (int j = 0; j < 8; j++) {
            float p0 = fast_exp2(fmaf(S[j][0], LOG2E, -mb_lo));
            float p1 = fast_exp2(fmaf(S[j][1], LOG2E, -mb_lo));
            float p2 = fast_exp2(fmaf(S[j][2], LOG2E, -mb_hi));
            float p3 = fast_exp2(fmaf(S[j][3], LOG2E, -mb_hi));
            rs_lo += p0 + p1;
            rs_hi += p2 + p3;
            __half2 hlo = __floats2half2_rn(p0, p1);
            __half2 hhi = __floats2half2_rn(p2, p3);
            P[j][0] = *reinterpret_cast<uint32_t*>(&hlo);
            P[j][1] = *reinterpret_cast<uint32_t*>(&hhi);
        }
        rs_lo += __shfl_xor_sync(0xffffffffu, rs_lo, 1);
        rs_lo += __shfl_xor_sync(0xffffffffu, rs_lo, 2);
        rs_hi += __shfl_xor_sync(0xffffffffu, rs_hi, 1);
        rs_hi += __shfl_xor_sync(0xffffffffu, rs_hi, 2);
        l_lo += rs_lo;
        l_hi += rs_hi;

        // ---- O += P V  (k = 64 keys in 4 chunks of 16) ---------------------
#pragma unroll
        for (int kc = 0; kc < 4; kc++) {
            uint32_t a[4] = {P[2 * kc][0], P[2 * kc][1],
                             P[2 * kc + 1][0], P[2 * kc + 1][1]};
#pragma unroll
            for (int np = 0; np < 4; np++) {     // d 16-col pairs
                uint32_t b0, b1, b2, b3;
                int off = (kc * 16 + v_rl) * 128 + np * 32 + v_colb;
                ldsm_x4_t(b0, b1, b2, b3, vs_base + SWZ(off));
                mma16816(Oacc[2 * np],     a, b0, b1);
                mma16816(Oacc[2 * np + 1], a, b2, b3);
            }
        }
        __syncthreads();
    }

    // ---- epilogue: normalize and write fp32 [B, N, DIM] --------------------
    const float inv_lo = 1.0f / l_lo;
    const float inv_hi = 1.0f / l_hi;
    const int r_lo = qt * 128 + warp * 16 + (lane >> 2);
    const int r_hi = r_lo + 8;
    const int dq   = 2 * (lane & 3);
#pragma unroll
    for (int j = 0; j < 8; j++) {
        const int d0 = j * 8 + dq;
        float2 vlo = make_float2(Oacc[j][0] * inv_lo, Oacc[j][1] * inv_lo);
        float2 vhi = make_float2(Oacc[j][2] * inv_hi, Oacc[j][3] * inv_hi);
        *reinterpret_cast<float2*>(
            &out[((size_t)b * SEQ + r_lo) * DIM + h * HDIM + d0]) = vlo;
        *reinterpret_cast<float2*>(
            &out[((size_t)b * SEQ + r_hi) * DIM + h * HDIM + d0]) = vhi;
    }
}

// ---------------------------------------------------------------------------
// launch
// ---------------------------------------------------------------------------
extern "C" void kernel_launch(void* const* d_in, const int* in_sizes, int n_in,
                              void* d_out, int out_size) {
    const float* x  = (const float*)d_in[0];
    const float* wq = (const float*)d_in[1];
    const float* bq = (const float*)d_in[2];
    const float* wk = (const float*)d_in[3];
    const float* bk = (const float*)d_in[4];
    const float* wv = (const float*)d_in[5];
    const float* bv = (const float*)d_in[6];
    float* out = (float*)d_out;

    __half* qbuf; cudaGetSymbolAddress((void**)&qbuf, g_Q);
    __half* kbuf; cudaGetSymbolAddress((void**)&kbuf, g_K);
    __half* vbuf; cudaGetSymbolAddress((void**)&vbuf, g_V);

    dim3 gemm_grid(MROWS / BM, DIM / BN);   // 64 x 6
    qkv_gemm_kernel<<<gemm_grid, 256>>>(x, wq, bq, qbuf, 0.125f);  // fold 1/sqrt(64)
    qkv_gemm_kernel<<<gemm_grid, 256>>>(x, wk, bk, kbuf, 1.0f);
    qkv_gemm_kernel<<<gemm_grid, 256>>>(x, wv, bv, vbuf, 1.0f);

    dim3 attn_grid(BATCH * NHEADS * (SEQ / 128));   // 768
    attn_kernel<<<attn_grid, 256>>>(qbuf, kbuf, vbuf, out);
}

// round 6
// speedup vs baseline: 5.9791x; 2.5862x over previous
#include <cuda_runtime.h>
#include <cuda_fp16.h>
#include <cstdint>

// ---------------------------------------------------------------------------
// Problem constants
// ---------------------------------------------------------------------------
#define BATCH   4
#define SEQ     2048
#define DIM     768
#define NHEADS  12
#define HDIM    64
#define MROWS   (BATCH * SEQ)          // 8192

// fp16 scratch
__device__ __half g_Q[BATCH * NHEADS * SEQ * HDIM];
__device__ __half g_K[BATCH * NHEADS * SEQ * HDIM];
__device__ __half g_V[BATCH * NHEADS * SEQ * HDIM];
__device__ __half g_Xh[MROWS * DIM];
__device__ __half g_Wh[3 * DIM * DIM];

#define SWZ(o) ((o) ^ (((o) >> 3) & 0x70))   // SW128 swizzle for 128B rows
#define LOG2E 1.4426950408889634f

// ---------------------------------------------------------------------------
// PTX helpers
// ---------------------------------------------------------------------------
__device__ __forceinline__ void ldsm_x4(uint32_t& r0, uint32_t& r1,
                                        uint32_t& r2, uint32_t& r3,
                                        uint32_t addr) {
    asm volatile("ldmatrix.sync.aligned.m8n8.x4.shared.b16 {%0,%1,%2,%3}, [%4];"
                 : "=r"(r0), "=r"(r1), "=r"(r2), "=r"(r3) : "r"(addr));
}

__device__ __forceinline__ void ldsm_x4_t(uint32_t& r0, uint32_t& r1,
                                          uint32_t& r2, uint32_t& r3,
                                          uint32_t addr) {
    asm volatile("ldmatrix.sync.aligned.m8n8.x4.trans.shared.b16 {%0,%1,%2,%3}, [%4];"
                 : "=r"(r0), "=r"(r1), "=r"(r2), "=r"(r3) : "r"(addr));
}

__device__ __forceinline__ void mma16816(float* c, const uint32_t* a,
                                         const uint32_t b0, const uint32_t b1) {
    asm volatile("mma.sync.aligned.m16n8k16.row.col.f32.f16.f16.f32 "
                 "{%0,%1,%2,%3}, {%4,%5,%6,%7}, {%8,%9}, {%0,%1,%2,%3};"
                 : "+f"(c[0]), "+f"(c[1]), "+f"(c[2]), "+f"(c[3])
                 : "r"(a[0]), "r"(a[1]), "r"(a[2]), "r"(a[3]), "r"(b0), "r"(b1));
}

__device__ __forceinline__ float fast_exp2(float x) {
    x = fmaxf(x, -120.f);
    float fn = rintf(x);
    float f  = x - fn;
    float p  = 1.3333558e-3f;
    p = fmaf(p, f, 9.6181291e-3f);
    p = fmaf(p, f, 5.5504109e-2f);
    p = fmaf(p, f, 2.4022651e-1f);
    p = fmaf(p, f, 6.9314718e-1f);
    p = fmaf(p, f, 1.0f);
    return __int_as_float(((int)fn + 127) << 23) * p;
}

// ---------------------------------------------------------------------------
// fp32 -> fp16 conversion (vectorized)
// ---------------------------------------------------------------------------
__global__ __launch_bounds__(256)
void f2h_kernel(const float* __restrict__ src, __half* __restrict__ dst, int n4) {
    int i = blockIdx.x * blockDim.x + threadIdx.x;
    if (i < n4) {
        float4 v = reinterpret_cast<const float4*>(src)[i];
        __half2 h0 = __floats2half2_rn(v.x, v.y);
        __half2 h1 = __floats2half2_rn(v.z, v.w);
        uint2 u;
        u.x = *reinterpret_cast<uint32_t*>(&h0);
        u.y = *reinterpret_cast<uint32_t*>(&h1);
        reinterpret_cast<uint2*>(dst)[i] = u;
    }
}

// ---------------------------------------------------------------------------
// fp16 tensor-core QKV projection:
//   out[m, c] = (sum_k x[m,k] * w[c,k] + bias[c]) * scale   (NT HGEMM)
// 128x128x64 tiles, 8 warps (4m x 2n), warp tile 32x64, fp32 accum.
// Epilogue scatters fp16 into [B,H,N,D].
// ---------------------------------------------------------------------------
__global__ __launch_bounds__(256)
void qkv_hgemm_kernel(const __half* __restrict__ X,
                      const __half* __restrict__ W,
                      const float* __restrict__ bias,
                      __half* __restrict__ dst,
                      float scale) {
    __shared__ __align__(16) char As[128 * 128];   // 128 rows x 64 halves
    __shared__ __align__(16) char Bs[128 * 128];
    __shared__ float bsm[128];

    const int tid  = threadIdx.x;
    const int lane = tid & 31;
    const int warp = tid >> 5;
    const int m0   = blockIdx.x * 128;
    const int c0   = blockIdx.y * 128;

    if (tid < 128) bsm[tid] = bias[c0 + tid];

    const uint32_t as_base = (uint32_t)__cvta_generic_to_shared(As);
    const uint32_t bs_base = (uint32_t)__cvta_generic_to_shared(Bs);

    const int grp = lane >> 3;
    const int l7  = lane & 7;
    const int wm  = warp >> 1;          // 0..3
    const int wn  = warp & 1;           // 0..1

    // ldmatrix addresses (constant across k-tiles except kc offset)
    const int a_row  = wm * 32 + ((grp & 1) << 3) + l7;   // + mf*16
    const int a_colb = (grp >> 1) << 4;
    const int b_row  = wn * 64 + ((grp >> 1) << 3) + l7;  // + np*16
    const int b_colb = (grp & 1) << 4;

    float acc[2][8][4];
#pragma unroll
    for (int mf = 0; mf < 2; mf++)
#pragma unroll
        for (int nf = 0; nf < 8; nf++)
#pragma unroll
            for (int r = 0; r < 4; r++) acc[mf][nf][r] = 0.f;

    // per-thread load mapping: 4 uint4 per tile per operand
    const int lr = tid >> 3;            // rows tid/8 .. +32 steps
    const int lc = tid & 7;             // 16B chunk within 128B row

    for (int k0 = 0; k0 < DIM; k0 += 64) {
        const uint4* ag = reinterpret_cast<const uint4*>(X + (size_t)m0 * DIM + k0);
        const uint4* bg = reinterpret_cast<const uint4*>(W + (size_t)c0 * DIM + k0);
#pragma unroll
        for (int i = 0; i < 4; i++) {
            const int row = lr + i * 32;
            const int off = row * 128 + lc * 16;
            *reinterpret_cast<uint4*>(As + SWZ(off)) = ag[row * (DIM / 8) + lc];
            *reinterpret_cast<uint4*>(Bs + SWZ(off)) = bg[row * (DIM / 8) + lc];
        }
        __syncthreads();

#pragma unroll
        for (int kc = 0; kc < 4; kc++) {
            uint32_t a[2][4];
#pragma unroll
            for (int mf = 0; mf < 2; mf++) {
                int off = (a_row + mf * 16) * 128 + kc * 32 + a_colb;
                ldsm_x4(a[mf][0], a[mf][1], a[mf][2], a[mf][3], as_base + SWZ(off));
            }
#pragma unroll
            for (int np = 0; np < 4; np++) {
                uint32_t b0, b1, b2, b3;
                int off = (b_row + np * 16) * 128 + kc * 32 + b_colb;
                ldsm_x4(b0, b1, b2, b3, bs_base + SWZ(off));
#pragma unroll
                for (int mf = 0; mf < 2; mf++) {
                    mma16816(acc[mf][2 * np],     a[mf], b0, b1);
                    mma16816(acc[mf][2 * np + 1], a[mf], b2, b3);
                }
            }
        }
        __syncthreads();
    }

    // epilogue: +bias, *scale, pack half2, scatter [B,H,N,D]
    const int h  = (c0 + wn * 64) >> 6;
    const int dq = 2 * (lane & 3);
    const int mbase = m0 + wm * 32 + (lane >> 2);
    const int b  = m0 >> 11;                 // whole block is in one batch
    __half* dbase = dst + ((size_t)(b * NHEADS + h) * SEQ) * HDIM;
#pragma unroll
    for (int mf = 0; mf < 2; mf++) {
        const int n0 = (mbase + mf * 16) & 2047;
        const int n1 = n0 + 8;
#pragma unroll
        for (int nf = 0; nf < 8; nf++) {
            const int d  = nf * 8 + dq;
            const float bv0 = bsm[wn * 64 + d];
            const float bv1 = bsm[wn * 64 + d + 1];
            __half2 lo = __floats2half2_rn((acc[mf][nf][0] + bv0) * scale,
                                           (acc[mf][nf][1] + bv1) * scale);
            __half2 hi = __floats2half2_rn((acc[mf][nf][2] + bv0) * scale,
                                           (acc[mf][nf][3] + bv1) * scale);
            *reinterpret_cast<__half2*>(dbase + (size_t)n0 * HDIM + d) = lo;
            *reinterpret_cast<__half2*>(dbase + (size_t)n1 * HDIM + d) = hi;
        }
    }
}

// ---------------------------------------------------------------------------
// Flash attention with fp16 mma.sync (unchanged from round 3 winner)
// ---------------------------------------------------------------------------
__global__ __launch_bounds__(256)
void attn_kernel(const __half* __restrict__ Q,
                 const __half* __restrict__ K,
                 const __half* __restrict__ V,
                 float* __restrict__ out /* [B,N,DIM] fp32 */) {
    __shared__ __align__(16) char qs[128 * 128];
    __shared__ __align__(16) char ks[64 * 128];
    __shared__ __align__(16) char vs[64 * 128];

    const int tid  = threadIdx.x;
    const int lane = tid & 31;
    const int warp = tid >> 5;

    const int nqt = SEQ / 128;
    const int bh  = blockIdx.x / nqt;
    const int qt  = blockIdx.x % nqt;
    const int b   = bh / NHEADS;
    const int h   = bh % NHEADS;

    const uint32_t qs_base = (uint32_t)__cvta_generic_to_shared(qs);
    const uint32_t ks_base = (uint32_t)__cvta_generic_to_shared(ks);
    const uint32_t vs_base = (uint32_t)__cvta_generic_to_shared(vs);

    {
        const uint4* g = reinterpret_cast<const uint4*>(
            Q + ((size_t)bh * SEQ + qt * 128) * HDIM);
#pragma unroll
        for (int c = tid; c < 1024; c += 256) {
            int off = c * 16;
            *reinterpret_cast<uint4*>(qs + SWZ(off)) = g[c];
        }
    }
    __syncthreads();

    const int grp = lane >> 3;
    const int l7  = lane & 7;

    uint32_t qa[4][4];
    {
        const int qrow  = warp * 16 + ((grp & 1) << 3) + l7;
        const int qcolb = (grp >> 1) << 4;
#pragma unroll
        for (int kc = 0; kc < 4; kc++) {
            int off = qrow * 128 + kc * 32 + qcolb;
            ldsm_x4(qa[kc][0], qa[kc][1], qa[kc][2], qa[kc][3], qs_base + SWZ(off));
        }
    }

    const int k_rl   = ((grp >> 1) << 3) + l7;
    const int k_colb = (grp & 1) << 4;
    const int v_rl   = ((grp & 1) << 3) + l7;
    const int v_colb = (grp >> 1) << 4;

    float Oacc[8][4];
#pragma unroll
    for (int j = 0; j < 8; j++)
#pragma unroll
        for (int r = 0; r < 4; r++) Oacc[j][r] = 0.f;
    float m_lo = -1e30f, m_hi = -1e30f, l_lo = 0.f, l_hi = 0.f;

    for (int kt = 0; kt < SEQ / 64; kt++) {
        const uint4* kg = reinterpret_cast<const uint4*>(
            K + ((size_t)bh * SEQ + kt * 64) * HDIM);
        const uint4* vg = reinterpret_cast<const uint4*>(
            V + ((size_t)bh * SEQ + kt * 64) * HDIM);
#pragma unroll
        for (int c = tid; c < 512; c += 256) {
            int off = c * 16;
            *reinterpret_cast<uint4*>(ks + SWZ(off)) = kg[c];
            *reinterpret_cast<uint4*>(vs + SWZ(off)) = vg[c];
        }
        __syncthreads();

        float S[8][4];
#pragma unroll
        for (int j = 0; j < 8; j++)
#pragma unroll
            for (int r = 0; r < 4; r++) S[j][r] = 0.f;

#pragma unroll
        for (int np = 0; np < 4; np++) {
#pragma unroll
            for (int kc = 0; kc < 4; kc++) {
                uint32_t b0, b1, b2, b3;
                int off = (np * 16 + k_rl) * 128 + kc * 32 + k_colb;
                ldsm_x4(b0, b1, b2, b3, ks_base + SWZ(off));
                mma16816(S[2 * np],     qa[kc], b0, b1);
                mma16816(S[2 * np + 1], qa[kc], b2, b3);
            }
        }

        float tmax_lo = -1e30f, tmax_hi = -1e30f;
#pragma unroll
        for (int j = 0; j < 8; j++) {
            tmax_lo = fmaxf(tmax_lo, fmaxf(S[j][0], S[j][1]));
            tmax_hi = fmaxf(tmax_hi, fmaxf(S[j][2], S[j][3]));
        }
        tmax_lo = fmaxf(tmax_lo, __shfl_xor_sync(0xffffffffu, tmax_lo, 1));
        tmax_lo = fmaxf(tmax_lo, __shfl_xor_sync(0xffffffffu, tmax_lo, 2));
        tmax_hi = fmaxf(tmax_hi, __shfl_xor_sync(0xffffffffu, tmax_hi, 1));
        tmax_hi = fmaxf(tmax_hi, __shfl_xor_sync(0xffffffffu, tmax_hi, 2));

        const float mnew_lo = fmaxf(m_lo, tmax_lo);
        const float mnew_hi = fmaxf(m_hi, tmax_hi);
        const float scl_lo = fast_exp2((m_lo - mnew_lo) * LOG2E);
        const float scl_hi = fast_exp2((m_hi - mnew_hi) * LOG2E);
        m_lo = mnew_lo;  m_hi = mnew_hi;
        l_lo *= scl_lo;  l_hi *= scl_hi;
#pragma unroll
        for (int j = 0; j < 8; j++) {
            Oacc[j][0] *= scl_lo; Oacc[j][1] *= scl_lo;
            Oacc[j][2] *= scl_hi; Oacc[j][3] *= scl_hi;
        }

        const float mb_lo = mnew_lo * LOG2E;
        const float mb_hi = mnew_hi * LOG2E;
        uint32_t P[8][2];
        float rs_lo = 0.f, rs_hi = 0.f;
#pragma unroll
        for (int j = 0; j < 8; j++) {
            float p0 = fast_exp2(fmaf(S[j][0], LOG2E, -mb_lo));
            float p1 = fast_exp2(fmaf(S[j][1], LOG2E, -mb_lo));
            float p2 = fast_exp2(fmaf(S[j][2], LOG2E, -mb_hi));
            float p3 = fast_exp2(fmaf(S[j][3], LOG2E, -mb_hi));
            rs_lo += p0 + p1;
            rs_hi += p2 + p3;
            __half2 hlo = __floats2half2_rn(p0, p1);
            __half2 hhi = __floats2half2_rn(p2, p3);
            P[j][0] = *reinterpret_cast<uint32_t*>(&hlo);
            P[j][1] = *reinterpret_cast<uint32_t*>(&hhi);
        }
        rs_lo += __shfl_xor_sync(0xffffffffu, rs_lo, 1);
        rs_lo += __shfl_xor_sync(0xffffffffu, rs_lo, 2);
        rs_hi += __shfl_xor_sync(0xffffffffu, rs_hi, 1);
        rs_hi += __shfl_xor_sync(0xffffffffu, rs_hi, 2);
        l_lo += rs_lo;
        l_hi += rs_hi;

#pragma unroll
        for (int kc = 0; kc < 4; kc++) {
            uint32_t a[4] = {P[2 * kc][0], P[2 * kc][1],
                             P[2 * kc + 1][0], P[2 * kc + 1][1]};
#pragma unroll
            for (int np = 0; np < 4; np++) {
                uint32_t b0, b1, b2, b3;
                int off = (kc * 16 + v_rl) * 128 + np * 32 + v_colb;
                ldsm_x4_t(b0, b1, b2, b3, vs_base + SWZ(off));
                mma16816(Oacc[2 * np],     a, b0, b1);
                mma16816(Oacc[2 * np + 1], a, b2, b3);
            }
        }
        __syncthreads();
    }

    const float inv_lo = 1.0f / l_lo;
    const float inv_hi = 1.0f / l_hi;
    const int r_lo = qt * 128 + warp * 16 + (lane >> 2);
    const int r_hi = r_lo + 8;
    const int dq   = 2 * (lane & 3);
#pragma unroll
    for (int j = 0; j < 8; j++) {
        const int d0 = j * 8 + dq;
        float2 vlo = make_float2(Oacc[j][0] * inv_lo, Oacc[j][1] * inv_lo);
        float2 vhi = make_float2(Oacc[j][2] * inv_hi, Oacc[j][3] * inv_hi);
        *reinterpret_cast<float2*>(
            &out[((size_t)b * SEQ + r_lo) * DIM + h * HDIM + d0]) = vlo;
        *reinterpret_cast<float2*>(
            &out[((size_t)b * SEQ + r_hi) * DIM + h * HDIM + d0]) = vhi;
    }
}

// ---------------------------------------------------------------------------
// launch
// ---------------------------------------------------------------------------
extern "C" void kernel_launch(void* const* d_in, const int* in_sizes, int n_in,
                              void* d_out, int out_size) {
    const float* x  = (const float*)d_in[0];
    const float* wq = (const float*)d_in[1];
    const float* bq = (const float*)d_in[2];
    const float* wk = (const float*)d_in[3];
    const float* bk = (const float*)d_in[4];
    const float* wv = (const float*)d_in[5];
    const float* bv = (const float*)d_in[6];
    float* out = (float*)d_out;

    __half* qbuf; cudaGetSymbolAddress((void**)&qbuf, g_Q);
    __half* kbuf; cudaGetSymbolAddress((void**)&kbuf, g_K);
    __half* vbuf; cudaGetSymbolAddress((void**)&vbuf, g_V);
    __half* xh;   cudaGetSymbolAddress((void**)&xh,   g_Xh);
    __half* wh;   cudaGetSymbolAddress((void**)&wh,   g_Wh);

    // fp32 -> fp16 conversions
    const int n4x = MROWS * DIM / 4;            // 1.57M
    const int n4w = DIM * DIM / 4;              // 147K
    f2h_kernel<<<(n4x + 255) / 256, 256>>>(x,  xh, n4x);
    f2h_kernel<<<(n4w + 255) / 256, 256>>>(wq, wh + 0 * DIM * DIM, n4w);
    f2h_kernel<<<(n4w + 255) / 256, 256>>>(wk, wh + 1 * DIM * DIM, n4w);
    f2h_kernel<<<(n4w + 255) / 256, 256>>>(wv, wh + 2 * DIM * DIM, n4w);

    // fp16 tensor-core projections (scale 1/8 folded into Q)
    dim3 gemm_grid(MROWS / 128, DIM / 128);     // 64 x 6
    qkv_hgemm_kernel<<<gemm_grid, 256>>>(xh, wh + 0 * DIM * DIM, bq, qbuf, 0.125f);
    qkv_hgemm_kernel<<<gemm_grid, 256>>>(xh, wh + 1 * DIM * DIM, bk, kbuf, 1.0f);
    qkv_hgemm_kernel<<<gemm_grid, 256>>>(xh, wh + 2 * DIM * DIM, bv, vbuf, 1.0f);

    dim3 attn_grid(BATCH * NHEADS * (SEQ / 128));
    attn_kernel<<<attn_grid, 256>>>(qbuf, kbuf, vbuf, out);
}

// round 8
// speedup vs baseline: 8.1716x; 1.3667x over previous
#include <cuda_runtime.h>
#include <cuda_fp16.h>
#include <cstdint>

// ---------------------------------------------------------------------------
// Problem constants
// ---------------------------------------------------------------------------
#define BATCH   4
#define SEQ     2048
#define DIM     768
#define NHEADS  12
#define HDIM    64
#define MROWS   (BATCH * SEQ)          // 8192

// fp16 scratch
__device__ __half g_Q[BATCH * NHEADS * SEQ * HDIM];
__device__ __half g_K[BATCH * NHEADS * SEQ * HDIM];
__device__ __half g_V[BATCH * NHEADS * SEQ * HDIM];
__device__ __half g_Xh[MROWS * DIM];
__device__ __half g_Wh[3 * DIM * DIM];

#define SWZ(o) ((o) ^ (((o) >> 3) & 0x70))   // SW128 swizzle for 128B rows
#define LOG2E 1.4426950408889634f

// ---------------------------------------------------------------------------
// PTX helpers
// ---------------------------------------------------------------------------
__device__ __forceinline__ void ldsm_x4(uint32_t& r0, uint32_t& r1,
                                        uint32_t& r2, uint32_t& r3,
                                        uint32_t addr) {
    asm volatile("ldmatrix.sync.aligned.m8n8.x4.shared.b16 {%0,%1,%2,%3}, [%4];"
                 : "=r"(r0), "=r"(r1), "=r"(r2), "=r"(r3) : "r"(addr));
}

__device__ __forceinline__ void ldsm_x4_t(uint32_t& r0, uint32_t& r1,
                                          uint32_t& r2, uint32_t& r3,
                                          uint32_t addr) {
    asm volatile("ldmatrix.sync.aligned.m8n8.x4.trans.shared.b16 {%0,%1,%2,%3}, [%4];"
                 : "=r"(r0), "=r"(r1), "=r"(r2), "=r"(r3) : "r"(addr));
}

__device__ __forceinline__ void mma16816(float* c, const uint32_t* a,
                                         const uint32_t b0, const uint32_t b1) {
    asm volatile("mma.sync.aligned.m16n8k16.row.col.f32.f16.f16.f32 "
                 "{%0,%1,%2,%3}, {%4,%5,%6,%7}, {%8,%9}, {%0,%1,%2,%3};"
                 : "+f"(c[0]), "+f"(c[1]), "+f"(c[2]), "+f"(c[3])
                 : "r"(a[0]), "r"(a[1]), "r"(a[2]), "r"(a[3]), "r"(b0), "r"(b1));
}

__device__ __forceinline__ void cp_async16(uint32_t dst, const void* src) {
    asm volatile("cp.async.cg.shared.global [%0], [%1], 16;" :: "r"(dst), "l"(src));
}
__device__ __forceinline__ void cp_commit() {
    asm volatile("cp.async.commit_group;");
}
__device__ __forceinline__ void cp_wait0() {
    asm volatile("cp.async.wait_group 0;");
}

__device__ __forceinline__ float fast_exp2(float x) {
    x = fmaxf(x, -120.f);
    float fn = rintf(x);
    float f  = x - fn;
    float p  = 1.3333558e-3f;
    p = fmaf(p, f, 9.6181291e-3f);
    p = fmaf(p, f, 5.5504109e-2f);
    p = fmaf(p, f, 2.4022651e-1f);
    p = fmaf(p, f, 6.9314718e-1f);
    p = fmaf(p, f, 1.0f);
    return __int_as_float(((int)fn + 127) << 23) * p;
}

// ---------------------------------------------------------------------------
// fp32 -> fp16 conversion (x: grid.y=0 path; weights: merged 3-way kernel)
// ---------------------------------------------------------------------------
__global__ __launch_bounds__(256)
void f2h_kernel(const float* __restrict__ src, __half* __restrict__ dst, int n4) {
    int i = blockIdx.x * blockDim.x + threadIdx.x;
    if (i < n4) {
        float4 v = reinterpret_cast<const float4*>(src)[i];
        __half2 h0 = __floats2half2_rn(v.x, v.y);
        __half2 h1 = __floats2half2_rn(v.z, v.w);
        uint2 u;
        u.x = *reinterpret_cast<uint32_t*>(&h0);
        u.y = *reinterpret_cast<uint32_t*>(&h1);
        reinterpret_cast<uint2*>(dst)[i] = u;
    }
}

__global__ __launch_bounds__(256)
void f2h_w_kernel(const float* __restrict__ wq, const float* __restrict__ wk,
                  const float* __restrict__ wv, __half* __restrict__ dst, int n4) {
    const int z = blockIdx.y;
    const float* src = z == 0 ? wq : (z == 1 ? wk : wv);
    int i = blockIdx.x * blockDim.x + threadIdx.x;
    if (i < n4) {
        float4 v = reinterpret_cast<const float4*>(src)[i];
        __half2 h0 = __floats2half2_rn(v.x, v.y);
        __half2 h1 = __floats2half2_rn(v.z, v.w);
        uint2 u;
        u.x = *reinterpret_cast<uint32_t*>(&h0);
        u.y = *reinterpret_cast<uint32_t*>(&h1);
        reinterpret_cast<uint2*>(dst + (size_t)z * DIM * DIM)[i] = u;
    }
}

// ---------------------------------------------------------------------------
// fp16 tensor-core QKV projection, cp.async double-buffered, grid.z = q/k/v.
//   out[m, c] = (sum_k x[m,k] * w[c,k] + bias[c]) * scale   (NT HGEMM)
// 128x128x64 tiles, 8 warps (4m x 2n), fp32 accum, dynamic smem 64.5 KB.
// ---------------------------------------------------------------------------
#define GEMM_SMEM (4 * 16384 + 512)

__global__ __launch_bounds__(256)
void qkv_hgemm_kernel(const __half* __restrict__ X,
                      const __half* __restrict__ Wall,
                      const float* __restrict__ bq_,
                      const float* __restrict__ bk_,
                      const float* __restrict__ bv_,
                      __half* __restrict__ Qd,
                      __half* __restrict__ Kd,
                      __half* __restrict__ Vd) {
    extern __shared__ __align__(16) char smem[];
    char* As = smem;                       // 2 stages x 16 KB
    char* Bs = smem + 32768;               // 2 stages x 16 KB
    float* bsm = reinterpret_cast<float*>(smem + 65536);

    const int z = blockIdx.z;
    const __half* W = Wall + (size_t)z * DIM * DIM;
    const float* bias = z == 0 ? bq_ : (z == 1 ? bk_ : bv_);
    __half* dst = z == 0 ? Qd : (z == 1 ? Kd : Vd);
    const float scale = z == 0 ? 0.125f : 1.0f;

    const int tid  = threadIdx.x;
    const int lane = tid & 31;
    const int warp = tid >> 5;
    const int m0   = blockIdx.x * 128;
    const int c0   = blockIdx.y * 128;

    if (tid < 128) bsm[tid] = bias[c0 + tid];

    const uint32_t as_base = (uint32_t)__cvta_generic_to_shared(As);
    const uint32_t bs_base = (uint32_t)__cvta_generic_to_shared(Bs);

    const int grp = lane >> 3;
    const int l7  = lane & 7;
    const int wm  = warp >> 1;
    const int wn  = warp & 1;

    const int a_row  = wm * 32 + ((grp & 1) << 3) + l7;
    const int a_colb = (grp >> 1) << 4;
    const int b_row  = wn * 64 + ((grp >> 1) << 3) + l7;
    const int b_colb = (grp & 1) << 4;

    float acc[2][8][4];
#pragma unroll
    for (int mf = 0; mf < 2; mf++)
#pragma unroll
        for (int nf = 0; nf < 8; nf++)
#pragma unroll
            for (int r = 0; r < 4; r++) acc[mf][nf][r] = 0.f;

    const int lr = tid >> 3;
    const int lc = tid & 7;

    auto issue_tile = [&](int kt, int s) {
        const char* ag = (const char*)(X + (size_t)m0 * DIM + kt * 64);
        const char* bg = (const char*)(W + (size_t)c0 * DIM + kt * 64);
        const uint32_t so = (uint32_t)s * 16384;
#pragma unroll
        for (int i = 0; i < 4; i++) {
            const int row = lr + i * 32;
            const int off = row * 128 + lc * 16;
            cp_async16(as_base + so + SWZ(off), ag + (size_t)row * (DIM * 2) + lc * 16);
            cp_async16(bs_base + so + SWZ(off), bg + (size_t)row * (DIM * 2) + lc * 16);
        }
    };

    issue_tile(0, 0);
    cp_commit();
    cp_wait0();
    __syncthreads();

    const int NKT = DIM / 64;   // 12
    for (int kt = 0; kt < NKT; kt++) {
        const int cur = kt & 1;
        if (kt + 1 < NKT) { issue_tile(kt + 1, cur ^ 1); cp_commit(); }

        const uint32_t aso = as_base + (uint32_t)cur * 16384;
        const uint32_t bso = bs_base + (uint32_t)cur * 16384;
#pragma unroll
        for (int kc = 0; kc < 4; kc++) {
            uint32_t a[2][4];
#pragma unroll
            for (int mf = 0; mf < 2; mf++) {
                int off = (a_row + mf * 16) * 128 + kc * 32 + a_colb;
                ldsm_x4(a[mf][0], a[mf][1], a[mf][2], a[mf][3], aso + SWZ(off));
            }
#pragma unroll
            for (int np = 0; np < 4; np++) {
                uint32_t b0, b1, b2, b3;
                int off = (b_row + np * 16) * 128 + kc * 32 + b_colb;
                ldsm_x4(b0, b1, b2, b3, bso + SWZ(off));
#pragma unroll
                for (int mf = 0; mf < 2; mf++) {
                    mma16816(acc[mf][2 * np],     a[mf], b0, b1);
                    mma16816(acc[mf][2 * np + 1], a[mf], b2, b3);
                }
            }
        }
        cp_wait0();
        __syncthreads();
    }

    // epilogue: +bias, *scale, pack half2, scatter [B,H,N,D]
    const int h  = (c0 + wn * 64) >> 6;
    const int dq = 2 * (lane & 3);
    const int mbase = m0 + wm * 32 + (lane >> 2);
    const int b  = m0 >> 11;
    __half* dbase = dst + ((size_t)(b * NHEADS + h) * SEQ) * HDIM;
#pragma unroll
    for (int mf = 0; mf < 2; mf++) {
        const int n0 = (mbase + mf * 16) & 2047;
        const int n1 = n0 + 8;
#pragma unroll
        for (int nf = 0; nf < 8; nf++) {
            const int d  = nf * 8 + dq;
            const float bv0 = bsm[wn * 64 + d];
            const float bv1 = bsm[wn * 64 + d + 1];
            __half2 lo = __floats2half2_rn((acc[mf][nf][0] + bv0) * scale,
                                           (acc[mf][nf][1] + bv1) * scale);
            __half2 hi = __floats2half2_rn((acc[mf][nf][2] + bv0) * scale,
                                           (acc[mf][nf][3] + bv1) * scale);
            *reinterpret_cast<__half2*>(dbase + (size_t)n0 * HDIM + d) = lo;
            *reinterpret_cast<__half2*>(dbase + (size_t)n1 * HDIM + d) = hi;
        }
    }
}

// ---------------------------------------------------------------------------
// Flash attention, fp16 mma.sync, cp.async double-buffered K/V tiles.
//   block = (b, h, 128 q-rows); 8 warps x 16 rows; 64-key tiles.
// ---------------------------------------------------------------------------
__global__ __launch_bounds__(256)
void attn_kernel(const __half* __restrict__ Q,
                 const __half* __restrict__ K,
                 const __half* __restrict__ V,
                 float* __restrict__ out /* [B,N,DIM] fp32 */) {
    __shared__ __align__(16) char qs[128 * 128];       // 16 KB
    __shared__ __align__(16) char ks[2][64 * 128];     // 2 x 8 KB
    __shared__ __align__(16) char vs[2][64 * 128];     // 2 x 8 KB

    const int tid  = threadIdx.x;
    const int lane = tid & 31;
    const int warp = tid >> 5;

    const int nqt = SEQ / 128;
    const int bh  = blockIdx.x / nqt;
    const int qt  = blockIdx.x % nqt;
    const int b   = bh / NHEADS;
    const int h   = bh % NHEADS;

    const uint32_t qs_base = (uint32_t)__cvta_generic_to_shared(qs);
    const uint32_t ks_base = (uint32_t)__cvta_generic_to_shared(ks);
    const uint32_t vs_base = (uint32_t)__cvta_generic_to_shared(vs);

    const char* Kbh = (const char*)(K + (size_t)bh * SEQ * HDIM);
    const char* Vbh = (const char*)(V + (size_t)bh * SEQ * HDIM);

    auto issue_kv = [&](int kt, int s) {
        const char* kg = Kbh + (size_t)kt * 64 * HDIM * 2;
        const char* vg = Vbh + (size_t)kt * 64 * HDIM * 2;
        const uint32_t so = (uint32_t)s * 8192;
#pragma unroll
        for (int c = tid; c < 512; c += 256) {
            const int off = c * 16;
            cp_async16(ks_base + so + SWZ(off), kg + off);
            cp_async16(vs_base + so + SWZ(off), vg + off);
        }
    };

    // stage Q + prefetch K/V tile 0 in one async group
    {
        const char* g = (const char*)(Q + ((size_t)bh * SEQ + qt * 128) * HDIM);
#pragma unroll
        for (int c = tid; c < 1024; c += 256)
            cp_async16(qs_base + SWZ(c * 16), g + c * 16);
    }
    issue_kv(0, 0);
    cp_commit();
    cp_wait0();
    __syncthreads();

    const int grp = lane >> 3;
    const int l7  = lane & 7;

    uint32_t qa[4][4];
    {
        const int qrow  = warp * 16 + ((grp & 1) << 3) + l7;
        const int qcolb = (grp >> 1) << 4;
#pragma unroll
        for (int kc = 0; kc < 4; kc++) {
            int off = qrow * 128 + kc * 32 + qcolb;
            ldsm_x4(qa[kc][0], qa[kc][1], qa[kc][2], qa[kc][3], qs_base + SWZ(off));
        }
    }

    const int k_rl   = ((grp >> 1) << 3) + l7;
    const int k_colb = (grp & 1) << 4;
    const int v_rl   = ((grp & 1) << 3) + l7;
    const int v_colb = (grp >> 1) << 4;

    float Oacc[8][4];
#pragma unroll
    for (int j = 0; j < 8; j++)
#pragma unroll
        for (int r = 0; r < 4; r++) Oacc[j][r] = 0.f;
    float m_lo = -1e30f, m_hi = -1e30f, l_lo = 0.f, l_hi = 0.f;

    const int NKT = SEQ / 64;   // 32
    for (int kt = 0; kt < NKT; kt++) {
        const int cur = kt & 1;
        if (kt + 1 < NKT) { issue_kv(kt + 1, cur ^ 1); cp_commit(); }

        const uint32_t kso = ks_base + (uint32_t)cur * 8192;
        const uint32_t vso = vs_base + (uint32_t)cur * 8192;

        // ---- S = Q K^T ----
        float S[8][4];
#pragma unroll
        for (int j = 0; j < 8; j++)
#pragma unroll
            for (int r = 0; r < 4; r++) S[j][r] = 0.f;

#pragma unroll
        for (int np = 0; np < 4; np++) {
#pragma unroll
            for (int kc = 0; kc < 4; kc++) {
                uint32_t b0, b1, b2, b3;
                int off = (np * 16 + k_rl) * 128 + kc * 32 + k_colb;
                ldsm_x4(b0, b1, b2, b3, kso + SWZ(off));
                mma16816(S[2 * np],     qa[kc], b0, b1);
                mma16816(S[2 * np + 1], qa[kc], b2, b3);
            }
        }

        // ---- online softmax ----
        float tmax_lo = -1e30f, tmax_hi = -1e30f;
#pragma unroll
        for (int j = 0; j < 8; j++) {
            tmax_lo = fmaxf(tmax_lo, fmaxf(S[j][0], S[j][1]));
            tmax_hi = fmaxf(tmax_hi, fmaxf(S[j][2], S[j][3]));
        }
        tmax_lo = fmaxf(tmax_lo, __shfl_xor_sync(0xffffffffu, tmax_lo, 1));
        tmax_lo = fmaxf(tmax_lo, __shfl_xor_sync(0xffffffffu, tmax_lo, 2));
        tmax_hi = fmaxf(tmax_hi, __shfl_xor_sync(0xffffffffu, tmax_hi, 1));
        tmax_hi = fmaxf(tmax_hi, __shfl_xor_sync(0xffffffffu, tmax_hi, 2));

        const float mnew_lo = fmaxf(m_lo, tmax_lo);
        const float mnew_hi = fmaxf(m_hi, tmax_hi);
        const float scl_lo = fast_exp2((m_lo - mnew_lo) * LOG2E);
        const float scl_hi = fast_exp2((m_hi - mnew_hi) * LOG2E);
        m_lo = mnew_lo;  m_hi = mnew_hi;
        l_lo *= scl_lo;  l_hi *= scl_hi;
#pragma unroll
        for (int j = 0; j < 8; j++) {
            Oacc[j][0] *= scl_lo; Oacc[j][1] *= scl_lo;
            Oacc[j][2] *= scl_hi; Oacc[j][3] *= scl_hi;
        }

        const float mb_lo = mnew_lo * LOG2E;
        const float mb_hi = mnew_hi * LOG2E;
        uint32_t P[8][2];
        float rs_lo = 0.f, rs_hi = 0.f;
#pragma unroll
        for (int j = 0; j < 8; j++) {
            float p0 = fast_exp2(fmaf(S[j][0], LOG2E, -mb_lo));
            float p1 = fast_exp2(fmaf(S[j][1], LOG2E, -mb_lo));
            float p2 = fast_exp2(fmaf(S[j][2], LOG2E, -mb_hi));
            float p3 = fast_exp2(fmaf(S[j][3], LOG2E, -mb_hi));
            rs_lo += p0 + p1;
            rs_hi += p2 + p3;
            __half2 hlo = __floats2half2_rn(p0, p1);
            __half2 hhi = __floats2half2_rn(p2, p3);
            P[j][0] = *reinterpret_cast<uint32_t*>(&hlo);
            P[j][1] = *reinterpret_cast<uint32_t*>(&hhi);
        }
        rs_lo += __shfl_xor_sync(0xffffffffu, rs_lo, 1);
        rs_lo += __shfl_xor_sync(0xffffffffu, rs_lo, 2);
        rs_hi += __shfl_xor_sync(0xffffffffu, rs_hi, 1);
        rs_hi += __shfl_xor_sync(0xffffffffu, rs_hi, 2);
        l_lo += rs_lo;
        l_hi += rs_hi;

        // ---- O += P V ----
#pragma unroll
        for (int kc = 0; kc < 4; kc++) {
            uint32_t a[4] = {P[2 * kc][0], P[2 * kc][1],
                             P[2 * kc + 1][0], P[2 * kc + 1][1]};
#pragma unroll
            for (int np = 0; np < 4; np++) {
                uint32_t b0, b1, b2, b3;
                int off = (kc * 16 + v_rl) * 128 + np * 32 + v_colb;
                ldsm_x4_t(b0, b1, b2, b3, vso + SWZ(off));
                mma16816(Oacc[2 * np],     a, b0, b1);
                mma16816(Oacc[2 * np + 1], a, b2, b3);
            }
        }

        cp_wait0();
        __syncthreads();
    }

    // ---- epilogue ----
    const float inv_lo = 1.0f / l_lo;
    const float inv_hi = 1.0f / l_hi;
    const int r_lo = qt * 128 + warp * 16 + (lane >> 2);
    const int r_hi = r_lo + 8;
    const int dq   = 2 * (lane & 3);
#pragma unroll
    for (int j = 0; j < 8; j++) {
        const int d0 = j * 8 + dq;
        float2 vlo = make_float2(Oacc[j][0] * inv_lo, Oacc[j][1] * inv_lo);
        float2 vhi = make_float2(Oacc[j][2] * inv_hi, Oacc[j][3] * inv_hi);
        *reinterpret_cast<float2*>(
            &out[((size_t)b * SEQ + r_lo) * DIM + h * HDIM + d0]) = vlo;
        *reinterpret_cast<float2*>(
            &out[((size_t)b * SEQ + r_hi) * DIM + h * HDIM + d0]) = vhi;
    }
}

// ---------------------------------------------------------------------------
// launch
// ---------------------------------------------------------------------------
extern "C" void kernel_launch(void* const* d_in, const int* in_sizes, int n_in,
                              void* d_out, int out_size) {
    const float* x  = (const float*)d_in[0];
    const float* wq = (const float*)d_in[1];
    const float* bq = (const float*)d_in[2];
    const float* wk = (const float*)d_in[3];
    const float* bk = (const float*)d_in[4];
    const float* wv = (const float*)d_in[5];
    const float* bv = (const float*)d_in[6];
    float* out = (float*)d_out;

    __half* qbuf; cudaGetSymbolAddress((void**)&qbuf, g_Q);
    __half* kbuf; cudaGetSymbolAddress((void**)&kbuf, g_K);
    __half* vbuf; cudaGetSymbolAddress((void**)&vbuf, g_V);
    __half* xh;   cudaGetSymbolAddress((void**)&xh,   g_Xh);
    __half* wh;   cudaGetSymbolAddress((void**)&wh,   g_Wh);

    static bool attr_set = false;
    if (!attr_set) {
        cudaFuncSetAttribute(qkv_hgemm_kernel,
                             cudaFuncAttributeMaxDynamicSharedMemorySize,
                             GEMM_SMEM);
        attr_set = true;
    }

    // fp32 -> fp16 conversions
    const int n4x = MROWS * DIM / 4;
    const int n4w = DIM * DIM / 4;
    f2h_kernel<<<(n4x + 255) / 256, 256>>>(x, xh, n4x);
    dim3 wgrid((n4w + 255) / 256, 3);
    f2h_w_kernel<<<wgrid, 256>>>(wq, wk, wv, wh, n4w);

    // fused fp16 tensor-core projections (z = q/k/v; 1/8 folded into Q)
    dim3 gemm_grid(MROWS / 128, DIM / 128, 3);   // 64 x 6 x 3
    qkv_hgemm_kernel<<<gemm_grid, 256, GEMM_SMEM>>>(
        xh, wh, bq, bk, bv, qbuf, kbuf, vbuf);

    dim3 attn_grid(BATCH * NHEADS * (SEQ / 128));
    attn_kernel<<<attn_grid, 256>>>(qbuf, kbuf, vbuf, out);
}